// round 13
// baseline (speedup 1.0000x reference)
#include <cuda_runtime.h>
#include <cuda_fp16.h>
#include <cstdint>
#include <math.h>

// Problem constants
#define B_SZ   2
#define S_LEN  2048
#define E_DIM  1024
#define H_NUM  16
#define D_HEAD 64
#define ALPHA  0.5f
#define LOG2E  1.4426950408889634f

#define GM 4096
#define GN 1024
#define GK 1024

// Scratch (device globals — allocation-free), all fp16
__device__ __half g_X [GM * GK];
__device__ __half g_Wq[GN * GK];         // Wq * 0.125*log2e
__device__ __half g_Wk[GN * GK];
__device__ __half g_Wv[GN * GK];
__device__ __half g_Wo[GN * GK];
__device__ __half g_Q [GM * GN];         // pre-scaled, [b*S+s][h*64+d]
__device__ __half g_K [GM * GN];         // [b*S+s][h*64+d]
__device__ __half g_V [GM * GN];         // TRANSPOSED: [(b*1024 + h*64+d)][s]
__device__ __half g_A [GM * GN];

// ---------------------------------------------------------------------------
// Helpers
// ---------------------------------------------------------------------------
static __device__ __forceinline__ uint32_t smem_u32(const void* p) {
    uint32_t a;
    asm("{ .reg .u64 t; cvta.to.shared.u64 t, %1; cvt.u32.u64 %0, t; }" : "=r"(a) : "l"(p));
    return a;
}
static __device__ __forceinline__ float ex2(float x) {
    float y;
    asm("ex2.approx.f32 %0, %1;" : "=f"(y) : "f"(x));
    return y;
}
static __device__ __forceinline__ uint32_t packh2(float a, float b) {
    __half2 h = __floats2half2_rn(a, b);
    return *(uint32_t*)&h;
}
static __device__ __forceinline__ void cp16(uint32_t dst, const void* src) {
    asm volatile("cp.async.cg.shared.global [%0], [%1], 16;" :: "r"(dst), "l"(src));
}
static __device__ __forceinline__ void cp_commit() {
    asm volatile("cp.async.commit_group;" ::: "memory");
}
static __device__ __forceinline__ void cp_wait0() {
    asm volatile("cp.async.wait_group 0;" ::: "memory");
}
static __device__ __forceinline__ void cp_wait1() {
    asm volatile("cp.async.wait_group 1;" ::: "memory");
}
#define LDSM4(R, ADDR)                                                        \
    asm volatile("ldmatrix.sync.aligned.m8n8.x4.shared.b16 {%0,%1,%2,%3}, [%4];" \
        : "=r"((R)[0]), "=r"((R)[1]), "=r"((R)[2]), "=r"((R)[3]) : "r"(ADDR))

// D += A(16x16) @ B(16x8), fp16 inputs, f32 accumulate
static __device__ __forceinline__ void mma8(float* d, const uint32_t* a,
                                            uint32_t b0, uint32_t b1) {
    asm volatile(
        "mma.sync.aligned.m16n8k16.row.col.f32.f16.f16.f32 "
        "{%0,%1,%2,%3}, {%4,%5,%6,%7}, {%8,%9}, {%0,%1,%2,%3};"
        : "+f"(d[0]), "+f"(d[1]), "+f"(d[2]), "+f"(d[3])
        : "r"(a[0]), "r"(a[1]), "r"(a[2]), "r"(a[3]), "r"(b0), "r"(b1));
}

// ---------------------------------------------------------------------------
// Pre-convert inputs to FP16 (scale folded for Wq)
// ---------------------------------------------------------------------------
__global__ __launch_bounds__(256)
void cvt_kernel(const float4* __restrict__ x,  const float4* __restrict__ wq,
                const float4* __restrict__ wk, const float4* __restrict__ wv,
                const float4* __restrict__ wo)
{
    const int z = blockIdx.z;
    const float4* src;
    __half2* dst;
    int n4;
    float s = 1.0f;
    switch (z) {
        case 0: src = x;  dst = (__half2*)g_X;  n4 = GM * GK / 4; break;
        case 1: src = wq; dst = (__half2*)g_Wq; n4 = GN * GK / 4; s = 0.125f * LOG2E; break;
        case 2: src = wk; dst = (__half2*)g_Wk; n4 = GN * GK / 4; break;
        case 3: src = wv; dst = (__half2*)g_Wv; n4 = GN * GK / 4; break;
        default: src = wo; dst = (__half2*)g_Wo; n4 = GN * GK / 4; break;
    }
    for (int i = blockIdx.x * 256 + threadIdx.x; i < n4; i += gridDim.x * 256) {
        float4 v = src[i];
        dst[2 * i]     = __floats2half2_rn(v.x * s, v.y * s);
        dst[2 * i + 1] = __floats2half2_rn(v.z * s, v.w * s);
    }
}

// ---------------------------------------------------------------------------
// FP16 GEMM (unchanged): C = A[M,K] @ W[N,K]^T, f32 accum.
// ---------------------------------------------------------------------------
#define GEMM_SMEM (3 * 32768)

__global__ __launch_bounds__(128, 2)
void gemm_tc(const __half* __restrict__ A,
             const __half* __restrict__ W0, const __half* __restrict__ W1,
             const __half* __restrict__ W2,
             void* __restrict__ C0, void* __restrict__ C1, void* __restrict__ C2,
             int cvt_out)
{
    extern __shared__ char smc[];
    const uint32_t sb = smem_u32(smc);

    const __half* W = (blockIdx.z == 0) ? W0 : (blockIdx.z == 1) ? W1 : W2;
    void*         C = (blockIdx.z == 0) ? C0 : (blockIdx.z == 1) ? C1 : C2;

    const int t    = threadIdx.x;
    const int w    = t >> 5;
    const int lane = t & 31;
    const int g    = lane >> 2;
    const int t4   = lane & 3;
    const int i7   = lane & 7;
    const int tq   = lane >> 3;
    const int m0   = (w >> 1) * 64;
    const int n0   = (w & 1) * 64;
    const int bm   = blockIdx.y * 128;
    const int bn   = blockIdx.x * 128;

    const uint32_t laneA = (uint32_t)(m0 + ((tq & 1) << 3) + i7) * 128;
    const uint32_t laneB = (uint32_t)(n0 + ((tq & 2) << 2) + i7) * 128;

    float acc[4][8][4];
#pragma unroll
    for (int mf = 0; mf < 4; mf++)
#pragma unroll
        for (int nf = 0; nf < 8; nf++)
#pragma unroll
            for (int r = 0; r < 4; r++) acc[mf][nf][r] = 0.0f;

#define GEMM_ISSUE(CH) do {                                                     \
        const int _k0 = (CH) * 64;                                              \
        const uint32_t _sa = sb + ((CH) % 3) * 32768;                           \
        _Pragma("unroll")                                                       \
        for (int _i = 0; _i < 8; _i++) {                                        \
            int _idx = _i * 128 + t;                                            \
            int _row = _idx >> 3;                                               \
            int _wd  = _idx & 7;                                                \
            uint32_t _o = (uint32_t)(_row * 128 + (((_wd) ^ (_row & 7)) << 4)); \
            cp16(_sa + _o,         &A[(size_t)(bm + _row) * GK + _k0 + _wd * 8]); \
            cp16(_sa + 16384 + _o, &W[(size_t)(bn + _row) * GK + _k0 + _wd * 8]); \
        }                                                                       \
        cp_commit();                                                            \
    } while (0)

    GEMM_ISSUE(0);
    GEMM_ISSUE(1);

    for (int ch = 0; ch < 16; ch++) {
        if (ch < 15) cp_wait1(); else cp_wait0();
        __syncthreads();
        if (ch + 2 < 16) GEMM_ISSUE(ch + 2);

        const uint32_t stage = sb + (ch % 3) * 32768;
#pragma unroll
        for (int ks = 0; ks < 4; ks++) {
            const uint32_t cwA = (uint32_t)(((2 * ks + (tq >> 1)) ^ i7) << 4);
            const uint32_t cwB = (uint32_t)(((2 * ks + (tq & 1)) ^ i7) << 4);
            uint32_t av[4][4];
#pragma unroll
            for (int mf = 0; mf < 4; mf++)
                LDSM4(av[mf], stage + laneA + mf * 2048 + cwA);
            uint32_t bv[16];
#pragma unroll
            for (int np = 0; np < 4; np++)
                LDSM4(&bv[np * 4], stage + 16384 + laneB + np * 2048 + cwB);
#pragma unroll
            for (int nf = 0; nf < 8; nf++) {
                uint32_t b0 = bv[(nf >> 1) * 4 + (nf & 1) * 2];
                uint32_t b1 = bv[(nf >> 1) * 4 + (nf & 1) * 2 + 1];
#pragma unroll
                for (int mf = 0; mf < 4; mf++)
                    mma8(acc[mf][nf], av[mf], b0, b1);
            }
        }
    }

    // epilogue
    if (cvt_out && blockIdx.z == 2) {
        __half* Ch = (__half*)C;
        const int bb = bm >> 11;
#pragma unroll
        for (int mf = 0; mf < 4; mf++) {
            int row = bm + m0 + mf * 16 + g;
            int s   = row & (S_LEN - 1);
#pragma unroll
            for (int nf = 0; nf < 8; nf++) {
                int col = bn + n0 + nf * 8 + 2 * t4;
                size_t base = ((size_t)(bb * 1024 + col)) * S_LEN + s;
                Ch[base]             = __float2half_rn(acc[mf][nf][0]);
                Ch[base + S_LEN]     = __float2half_rn(acc[mf][nf][1]);
                Ch[base + 8]         = __float2half_rn(acc[mf][nf][2]);
                Ch[base + S_LEN + 8] = __float2half_rn(acc[mf][nf][3]);
            }
        }
    } else if (cvt_out) {
        __half* Ch = (__half*)C;
#pragma unroll
        for (int mf = 0; mf < 4; mf++) {
            int row = bm + m0 + mf * 16 + g;
#pragma unroll
            for (int nf = 0; nf < 8; nf++) {
                int col = bn + n0 + nf * 8 + 2 * t4;
                *(__half2*)&Ch[(size_t)row * GN + col] =
                    __floats2half2_rn(acc[mf][nf][0], acc[mf][nf][1]);
                *(__half2*)&Ch[(size_t)(row + 8) * GN + col] =
                    __floats2half2_rn(acc[mf][nf][2], acc[mf][nf][3]);
            }
        }
    } else {
        float* Cf = (float*)C;
#pragma unroll
        for (int mf = 0; mf < 4; mf++) {
            int row = bm + m0 + mf * 16 + g;
#pragma unroll
            for (int nf = 0; nf < 8; nf++) {
                int col = bn + n0 + nf * 8 + 2 * t4;
                *(float2*)&Cf[(size_t)row * GN + col] =
                    make_float2(acc[mf][nf][0], acc[mf][nf][1]);
                *(float2*)&Cf[(size_t)(row + 8) * GN + col] =
                    make_float2(acc[mf][nf][2], acc[mf][nf][3]);
            }
        }
    }
#undef GEMM_ISSUE
}

// ---------------------------------------------------------------------------
// FP16 flash attention, SOFTWARE-PIPELINED across KV tiles:
//   iter kt: softmax(kt) -> [ PV(kt)  ||  QK(kt+1) ]  (fused ks loop,
//   two independent tensor chains interleaved by the scheduler).
// q-tile 64, 4 warps x 16 rows, register-resident P, no-max exp2 softmax.
// K prefetched TWO tiles ahead, V one tile ahead (both double-buffered).
// SMEM: Q @0 (8K), K0 @8192, K1 @16384, V0 @24576, V1 @32768 (8K each),
//       madd @40960 (512B).  Total 41,472 B -> 3 CTAs/SM.
// ---------------------------------------------------------------------------
#define ATT_SMEM 41472

__global__ __launch_bounds__(128, 3)
void attn_tc(const unsigned int* __restrict__ mask, __half* __restrict__ out)
{
    extern __shared__ char smc[];
    const uint32_t sb  = smem_u32(smc);
    const uint32_t QB  = sb;
    const uint32_t KB0 = sb + 8192;
    const uint32_t VB0 = sb + 24576;
    float* maddf = (float*)(smc + 40960);

    const int t    = threadIdx.x;
    const int w    = t >> 5;
    const int lane = t & 31;
    const int g    = lane >> 2;
    const int t4   = lane & 3;
    const int i7   = lane & 7;
    const int tq   = lane >> 3;
    const int q0   = blockIdx.x * 64;
    const int h    = blockIdx.y;
    const int b    = blockIdx.z;
    const int m0   = w * 16;

    const float BSC = ALPHA * LOG2E / (float)S_LEN;

    const uint32_t laneA = (uint32_t)(m0 + ((tq & 1) << 3) + i7) * 128;   // Q
    const uint32_t laneB = (uint32_t)(((tq & 2) << 2) + i7) * 128;        // K, V^T

    // prologue: one group {Q, K(0), K(1), V(0)}; madd[0]
#pragma unroll
    for (int i = 0; i < 4; i++) {
        int idx = i * 128 + t;
        int row = idx >> 3;
        int wd  = idx & 7;
        uint32_t so = (uint32_t)(row * 128 + ((wd ^ (row & 7)) << 4));
        cp16(QB + so, &g_Q[((size_t)(b * S_LEN + q0 + row)) * E_DIM + h * D_HEAD + wd * 8]);
        cp16(KB0 + so, &g_K[((size_t)(b * S_LEN + row)) * E_DIM + h * D_HEAD + wd * 8]);
        cp16(KB0 + 8192 + so,
             &g_K[((size_t)(b * S_LEN + 64 + row)) * E_DIM + h * D_HEAD + wd * 8]);
        cp16(VB0 + so, &g_V[((size_t)(b * 1024 + h * D_HEAD + row)) * S_LEN + wd * 8]);
    }
    cp_commit();
    if (t < 64)
        maddf[t] = (mask[b * S_LEN + t] != 0u) ? -1e30f : 0.0f;
    cp_wait0();
    __syncthreads();

    float o[8][4];
#pragma unroll
    for (int nf = 0; nf < 8; nf++)
#pragma unroll
        for (int r = 0; r < 4; r++) o[nf][r] = 0.0f;

    float lp0 = 0.0f, lp1 = 0.0f;
    const float tgtA = (float)(S_LEN - 1 - (q0 + m0 + g));
    const float tgtB = tgtA - 8.0f;

    // ---- QK(0) into sc (pre-loop) ----
    float sc[8][4];
#pragma unroll
    for (int nf = 0; nf < 8; nf++)
#pragma unroll
        for (int r = 0; r < 4; r++) sc[nf][r] = 0.0f;
#pragma unroll
    for (int ks = 0; ks < 4; ks++) {
        const uint32_t cwA = (uint32_t)(((2 * ks + (tq >> 1)) ^ i7) << 4);
        const uint32_t cwB = (uint32_t)(((2 * ks + (tq & 1)) ^ i7) << 4);
        uint32_t av[4];
        LDSM4(av, QB + laneA + cwA);
        uint32_t bv[16];
#pragma unroll
        for (int np = 0; np < 4; np++)
            LDSM4(&bv[np * 4], KB0 + laneB + np * 2048 + cwB);
#pragma unroll
        for (int nf = 0; nf < 8; nf++)
            mma8(sc[nf], av, bv[(nf >> 1) * 4 + (nf & 1) * 2],
                            bv[(nf >> 1) * 4 + (nf & 1) * 2 + 1]);
    }

    for (int kt = 0; kt < 32; kt++) {
        const int k0g = kt * 64;
        const uint32_t VBc = VB0 + ((uint32_t)(kt & 1) << 13);      // V(kt)
        const uint32_t KBn = KB0 + ((uint32_t)((kt + 1) & 1) << 13); // K(kt+1)

        // sync: group from iter kt-1 {K(kt+1), V(kt)} complete + visible;
        // protects buffer overwrites (all warps past QK(kt) / PV(kt-1)).
        if (kt) cp_wait0();
        __syncthreads();

        // prefetch K(kt+2) -> KB(kt&1), V(kt+1) -> VB((kt+1)&1), madd(kt+1)
        if (kt < 31) {
#pragma unroll
            for (int i = 0; i < 4; i++) {
                int idx = i * 128 + t;
                int row = idx >> 3;
                int wd  = idx & 7;
                uint32_t so = (uint32_t)(row * 128 + ((wd ^ (row & 7)) << 4));
                if (kt < 30)
                    cp16(KB0 + ((uint32_t)(kt & 1) << 13) + so,
                         &g_K[((size_t)(b * S_LEN + k0g + 128 + row)) * E_DIM + h * D_HEAD + wd * 8]);
                cp16(VB0 + ((uint32_t)((kt + 1) & 1) << 13) + so,
                     &g_V[((size_t)(b * 1024 + h * D_HEAD + row)) * S_LEN + k0g + 64 + wd * 8]);
            }
            cp_commit();
            if (t < 64)
                maddf[((kt + 1) & 1) * 64 + t] =
                    (mask[b * S_LEN + k0g + 64 + t] != 0u) ? -1e30f : 0.0f;
        }

        // ---- softmax(kt): sc -> pa (register P), partial sums ----
        const float* md = maddf + (kt & 1) * 64;
        uint32_t pa[16];
        {
            float s0 = 0.0f, s1 = 0.0f;
#pragma unroll
            for (int nf = 0; nf < 8; nf++) {
                int jc = nf * 8 + 2 * t4;
                float jk0 = (float)(k0g + jc);
                float2 ma = *(const float2*)&md[jc];
                float p0 = ex2(sc[nf][0] - BSC * fabsf(jk0 - tgtA) + ma.x);
                float p1 = ex2(sc[nf][1] - BSC * fabsf(jk0 + 1.0f - tgtA) + ma.y);
                float p2 = ex2(sc[nf][2] - BSC * fabsf(jk0 - tgtB) + ma.x);
                float p3 = ex2(sc[nf][3] - BSC * fabsf(jk0 + 1.0f - tgtB) + ma.y);
                s0 += p0 + p1;
                s1 += p2 + p3;
                pa[2 * nf]     = packh2(p0, p1);
                pa[2 * nf + 1] = packh2(p2, p3);
                // reset sc for QK(kt+1) accumulation
                sc[nf][0] = 0.0f; sc[nf][1] = 0.0f;
                sc[nf][2] = 0.0f; sc[nf][3] = 0.0f;
            }
            lp0 += s0;
            lp1 += s1;
        }

        // ---- fused: PV(kt) [pa @ V(kt)]  ||  QK(kt+1) [Q @ K(kt+1)] ----
        if (kt < 31) {
#pragma unroll
            for (int ks = 0; ks < 4; ks++) {
                const uint32_t cwA = (uint32_t)(((2 * ks + (tq >> 1)) ^ i7) << 4);
                const uint32_t cwB = (uint32_t)(((2 * ks + (tq & 1)) ^ i7) << 4);
                uint32_t av[4];
                LDSM4(av, QB + laneA + cwA);
                uint32_t bk[16], bvv[16];
#pragma unroll
                for (int np = 0; np < 4; np++) {
                    LDSM4(&bk[np * 4],  KBn + laneB + np * 2048 + cwB);
                    LDSM4(&bvv[np * 4], VBc + laneB + np * 2048 + cwB);
                }
#pragma unroll
                for (int nf = 0; nf < 8; nf++) {
                    int bi = (nf >> 1) * 4 + (nf & 1) * 2;
                    mma8(sc[nf], av, bk[bi], bk[bi + 1]);         // QK(kt+1)
                    mma8(o[nf], &pa[4 * ks], bvv[bi], bvv[bi + 1]); // PV(kt)
                }
            }
        } else {
            // last tile: PV only
#pragma unroll
            for (int ks = 0; ks < 4; ks++) {
                const uint32_t cwB = (uint32_t)(((2 * ks + (tq & 1)) ^ i7) << 4);
                uint32_t bvv[16];
#pragma unroll
                for (int np = 0; np < 4; np++)
                    LDSM4(&bvv[np * 4], VBc + laneB + np * 2048 + cwB);
#pragma unroll
                for (int nf = 0; nf < 8; nf++) {
                    int bi = (nf >> 1) * 4 + (nf & 1) * 2;
                    mma8(o[nf], &pa[4 * ks], bvv[bi], bvv[bi + 1]);
                }
            }
        }
    }

    // ---- final row-sum reduction, normalize, write fp16 ----
    lp0 += __shfl_xor_sync(0xffffffffu, lp0, 1);
    lp0 += __shfl_xor_sync(0xffffffffu, lp0, 2);
    lp1 += __shfl_xor_sync(0xffffffffu, lp1, 1);
    lp1 += __shfl_xor_sync(0xffffffffu, lp1, 2);
    float inv0 = 1.0f / lp0;
    float inv1 = 1.0f / lp1;
    size_t r0 = ((size_t)(b * S_LEN + q0 + m0 + g)) * E_DIM + h * D_HEAD;
    size_t r1 = r0 + 8 * E_DIM;
#pragma unroll
    for (int nf = 0; nf < 8; nf++) {
        int col = nf * 8 + 2 * t4;
        *(__half2*)&out[r0 + col] =
            __floats2half2_rn(o[nf][0] * inv0, o[nf][1] * inv0);
        *(__half2*)&out[r1 + col] =
            __floats2half2_rn(o[nf][2] * inv1, o[nf][3] * inv1);
    }
}

// ---------------------------------------------------------------------------
extern "C" void kernel_launch(void* const* d_in, const int* in_sizes, int n_in,
                              void* d_out, int out_size)
{
    const float* x    = (const float*)d_in[0];
    const float* Wq   = (const float*)d_in[1];
    const float* Wk   = (const float*)d_in[2];
    const float* Wv   = (const float*)d_in[3];
    const float* Wo   = (const float*)d_in[4];
    const unsigned int* mask = (const unsigned int*)d_in[5];
    float* out = (float*)d_out;

    __half *xp, *wqp, *wkp, *wvp, *wop, *qp, *kp, *vp, *ap;
    cudaGetSymbolAddress((void**)&xp,  g_X);
    cudaGetSymbolAddress((void**)&wqp, g_Wq);
    cudaGetSymbolAddress((void**)&wkp, g_Wk);
    cudaGetSymbolAddress((void**)&wvp, g_Wv);
    cudaGetSymbolAddress((void**)&wop, g_Wo);
    cudaGetSymbolAddress((void**)&qp,  g_Q);
    cudaGetSymbolAddress((void**)&kp,  g_K);
    cudaGetSymbolAddress((void**)&vp,  g_V);
    cudaGetSymbolAddress((void**)&ap,  g_A);

    cudaFuncSetAttribute(gemm_tc, cudaFuncAttributeMaxDynamicSharedMemorySize, GEMM_SMEM);
    cudaFuncSetAttribute(attn_tc, cudaFuncAttributeMaxDynamicSharedMemorySize, ATT_SMEM);

    // 1. pre-convert inputs to fp16 (Wq scaled by 0.125*log2e)
    cvt_kernel<<<dim3(512, 1, 5), 256>>>((const float4*)x, (const float4*)Wq,
                                         (const float4*)Wk, (const float4*)Wv,
                                         (const float4*)Wo);

    // 2. fused QKV projections (V written transposed)
    gemm_tc<<<dim3(GN / 128, GM / 128, 3), 128, GEMM_SMEM>>>(
        xp, wqp, wkp, wvp, qp, kp, vp, 1);

    // 3. attention (pipelined QK/PV overlap)
    attn_tc<<<dim3(S_LEN / 64, H_NUM, B_SZ), 128, ATT_SMEM>>>(mask, ap);

    // 4. output projection (fp32 out)
    gemm_tc<<<dim3(GN / 128, GM / 128, 1), 128, GEMM_SMEM>>>(
        ap, wop, wop, wop, out, out, out, 0);
}

// round 14
// speedup vs baseline: 1.0312x; 1.0312x over previous
#include <cuda_runtime.h>
#include <cuda_fp16.h>
#include <cstdint>
#include <math.h>

// Problem constants
#define B_SZ   2
#define S_LEN  2048
#define E_DIM  1024
#define H_NUM  16
#define D_HEAD 64
#define ALPHA  0.5f
#define LOG2E  1.4426950408889634f

#define GM 4096
#define GN 1024
#define GK 1024

// Scratch (device globals — allocation-free), all fp16
__device__ __half g_X [GM * GK];
__device__ __half g_Wq[GN * GK];         // Wq * 0.125*log2e
__device__ __half g_Wk[GN * GK];
__device__ __half g_Wv[GN * GK];
__device__ __half g_Wo[GN * GK];
__device__ __half g_Q [GM * GN];         // pre-scaled, [b*S+s][h*64+d]
__device__ __half g_K [GM * GN];         // [b*S+s][h*64+d]
__device__ __half g_V [GM * GN];         // TRANSPOSED: [(b*1024 + h*64+d)][s]
__device__ __half g_A [GM * GN];

// ---------------------------------------------------------------------------
// Helpers
// ---------------------------------------------------------------------------
static __device__ __forceinline__ uint32_t smem_u32(const void* p) {
    uint32_t a;
    asm("{ .reg .u64 t; cvta.to.shared.u64 t, %1; cvt.u32.u64 %0, t; }" : "=r"(a) : "l"(p));
    return a;
}
static __device__ __forceinline__ float ex2(float x) {
    float y;
    asm("ex2.approx.f32 %0, %1;" : "=f"(y) : "f"(x));
    return y;
}
static __device__ __forceinline__ uint32_t packh2(float a, float b) {
    __half2 h = __floats2half2_rn(a, b);
    return *(uint32_t*)&h;
}
static __device__ __forceinline__ void cp16(uint32_t dst, const void* src) {
    asm volatile("cp.async.cg.shared.global [%0], [%1], 16;" :: "r"(dst), "l"(src));
}
static __device__ __forceinline__ void cp_commit() {
    asm volatile("cp.async.commit_group;" ::: "memory");
}
static __device__ __forceinline__ void cp_wait0() {
    asm volatile("cp.async.wait_group 0;" ::: "memory");
}
static __device__ __forceinline__ void cp_wait1() {
    asm volatile("cp.async.wait_group 1;" ::: "memory");
}
#define LDSM4(R, ADDR)                                                        \
    asm volatile("ldmatrix.sync.aligned.m8n8.x4.shared.b16 {%0,%1,%2,%3}, [%4];" \
        : "=r"((R)[0]), "=r"((R)[1]), "=r"((R)[2]), "=r"((R)[3]) : "r"(ADDR))

// D += A(16x16) @ B(16x8), fp16 inputs, f32 accumulate
static __device__ __forceinline__ void mma8(float* d, const uint32_t* a,
                                            uint32_t b0, uint32_t b1) {
    asm volatile(
        "mma.sync.aligned.m16n8k16.row.col.f32.f16.f16.f32 "
        "{%0,%1,%2,%3}, {%4,%5,%6,%7}, {%8,%9}, {%0,%1,%2,%3};"
        : "+f"(d[0]), "+f"(d[1]), "+f"(d[2]), "+f"(d[3])
        : "r"(a[0]), "r"(a[1]), "r"(a[2]), "r"(a[3]), "r"(b0), "r"(b1));
}

// ---------------------------------------------------------------------------
// Pre-convert inputs to FP16 (scale folded for Wq)
// ---------------------------------------------------------------------------
__global__ __launch_bounds__(256)
void cvt_kernel(const float4* __restrict__ x,  const float4* __restrict__ wq,
                const float4* __restrict__ wk, const float4* __restrict__ wv,
                const float4* __restrict__ wo)
{
    const int z = blockIdx.z;
    const float4* src;
    __half2* dst;
    int n4;
    float s = 1.0f;
    switch (z) {
        case 0: src = x;  dst = (__half2*)g_X;  n4 = GM * GK / 4; break;
        case 1: src = wq; dst = (__half2*)g_Wq; n4 = GN * GK / 4; s = 0.125f * LOG2E; break;
        case 2: src = wk; dst = (__half2*)g_Wk; n4 = GN * GK / 4; break;
        case 3: src = wv; dst = (__half2*)g_Wv; n4 = GN * GK / 4; break;
        default: src = wo; dst = (__half2*)g_Wo; n4 = GN * GK / 4; break;
    }
    for (int i = blockIdx.x * 256 + threadIdx.x; i < n4; i += gridDim.x * 256) {
        float4 v = src[i];
        dst[2 * i]     = __floats2half2_rn(v.x * s, v.y * s);
        dst[2 * i + 1] = __floats2half2_rn(v.z * s, v.w * s);
    }
}

// ---------------------------------------------------------------------------
// FP16 GEMM (unchanged): C = A[M,K] @ W[N,K]^T, f32 accum.
// ---------------------------------------------------------------------------
#define GEMM_SMEM (3 * 32768)

__global__ __launch_bounds__(128, 2)
void gemm_tc(const __half* __restrict__ A,
             const __half* __restrict__ W0, const __half* __restrict__ W1,
             const __half* __restrict__ W2,
             void* __restrict__ C0, void* __restrict__ C1, void* __restrict__ C2,
             int cvt_out)
{
    extern __shared__ char smc[];
    const uint32_t sb = smem_u32(smc);

    const __half* W = (blockIdx.z == 0) ? W0 : (blockIdx.z == 1) ? W1 : W2;
    void*         C = (blockIdx.z == 0) ? C0 : (blockIdx.z == 1) ? C1 : C2;

    const int t    = threadIdx.x;
    const int w    = t >> 5;
    const int lane = t & 31;
    const int g    = lane >> 2;
    const int t4   = lane & 3;
    const int i7   = lane & 7;
    const int tq   = lane >> 3;
    const int m0   = (w >> 1) * 64;
    const int n0   = (w & 1) * 64;
    const int bm   = blockIdx.y * 128;
    const int bn   = blockIdx.x * 128;

    const uint32_t laneA = (uint32_t)(m0 + ((tq & 1) << 3) + i7) * 128;
    const uint32_t laneB = (uint32_t)(n0 + ((tq & 2) << 2) + i7) * 128;

    float acc[4][8][4];
#pragma unroll
    for (int mf = 0; mf < 4; mf++)
#pragma unroll
        for (int nf = 0; nf < 8; nf++)
#pragma unroll
            for (int r = 0; r < 4; r++) acc[mf][nf][r] = 0.0f;

#define GEMM_ISSUE(CH) do {                                                     \
        const int _k0 = (CH) * 64;                                              \
        const uint32_t _sa = sb + ((CH) % 3) * 32768;                           \
        _Pragma("unroll")                                                       \
        for (int _i = 0; _i < 8; _i++) {                                        \
            int _idx = _i * 128 + t;                                            \
            int _row = _idx >> 3;                                               \
            int _wd  = _idx & 7;                                                \
            uint32_t _o = (uint32_t)(_row * 128 + (((_wd) ^ (_row & 7)) << 4)); \
            cp16(_sa + _o,         &A[(size_t)(bm + _row) * GK + _k0 + _wd * 8]); \
            cp16(_sa + 16384 + _o, &W[(size_t)(bn + _row) * GK + _k0 + _wd * 8]); \
        }                                                                       \
        cp_commit();                                                            \
    } while (0)

    GEMM_ISSUE(0);
    GEMM_ISSUE(1);

    for (int ch = 0; ch < 16; ch++) {
        if (ch < 15) cp_wait1(); else cp_wait0();
        __syncthreads();
        if (ch + 2 < 16) GEMM_ISSUE(ch + 2);

        const uint32_t stage = sb + (ch % 3) * 32768;
#pragma unroll
        for (int ks = 0; ks < 4; ks++) {
            const uint32_t cwA = (uint32_t)(((2 * ks + (tq >> 1)) ^ i7) << 4);
            const uint32_t cwB = (uint32_t)(((2 * ks + (tq & 1)) ^ i7) << 4);
            uint32_t av[4][4];
#pragma unroll
            for (int mf = 0; mf < 4; mf++)
                LDSM4(av[mf], stage + laneA + mf * 2048 + cwA);
            uint32_t bv[16];
#pragma unroll
            for (int np = 0; np < 4; np++)
                LDSM4(&bv[np * 4], stage + 16384 + laneB + np * 2048 + cwB);
#pragma unroll
            for (int nf = 0; nf < 8; nf++) {
                uint32_t b0 = bv[(nf >> 1) * 4 + (nf & 1) * 2];
                uint32_t b1 = bv[(nf >> 1) * 4 + (nf & 1) * 2 + 1];
#pragma unroll
                for (int mf = 0; mf < 4; mf++)
                    mma8(acc[mf][nf], av[mf], b0, b1);
            }
        }
    }

    // epilogue
    if (cvt_out && blockIdx.z == 2) {
        __half* Ch = (__half*)C;
        const int bb = bm >> 11;
#pragma unroll
        for (int mf = 0; mf < 4; mf++) {
            int row = bm + m0 + mf * 16 + g;
            int s   = row & (S_LEN - 1);
#pragma unroll
            for (int nf = 0; nf < 8; nf++) {
                int col = bn + n0 + nf * 8 + 2 * t4;
                size_t base = ((size_t)(bb * 1024 + col)) * S_LEN + s;
                Ch[base]             = __float2half_rn(acc[mf][nf][0]);
                Ch[base + S_LEN]     = __float2half_rn(acc[mf][nf][1]);
                Ch[base + 8]         = __float2half_rn(acc[mf][nf][2]);
                Ch[base + S_LEN + 8] = __float2half_rn(acc[mf][nf][3]);
            }
        }
    } else if (cvt_out) {
        __half* Ch = (__half*)C;
#pragma unroll
        for (int mf = 0; mf < 4; mf++) {
            int row = bm + m0 + mf * 16 + g;
#pragma unroll
            for (int nf = 0; nf < 8; nf++) {
                int col = bn + n0 + nf * 8 + 2 * t4;
                *(__half2*)&Ch[(size_t)row * GN + col] =
                    __floats2half2_rn(acc[mf][nf][0], acc[mf][nf][1]);
                *(__half2*)&Ch[(size_t)(row + 8) * GN + col] =
                    __floats2half2_rn(acc[mf][nf][2], acc[mf][nf][3]);
            }
        }
    } else {
        float* Cf = (float*)C;
#pragma unroll
        for (int mf = 0; mf < 4; mf++) {
            int row = bm + m0 + mf * 16 + g;
#pragma unroll
            for (int nf = 0; nf < 8; nf++) {
                int col = bn + n0 + nf * 8 + 2 * t4;
                *(float2*)&Cf[(size_t)row * GN + col] =
                    make_float2(acc[mf][nf][0], acc[mf][nf][1]);
                *(float2*)&Cf[(size_t)(row + 8) * GN + col] =
                    make_float2(acc[mf][nf][2], acc[mf][nf][3]);
            }
        }
    }
#undef GEMM_ISSUE
}

// ---------------------------------------------------------------------------
// FP16 flash attention, KEY-SPLIT warps: 256 threads = 4 q-groups x 2 key
// halves.  Each warp: 16 q-rows x 32 keys per tile (half the mma/ex2/LDSM of
// round 12 per warp, no B-fragment duplication).  No-max exp2 softmax makes
// the key split exactly additive: partial unnormalized O + partial row sums
// combined once at the end through smem.  Register-resident P; K/V double-
// buffered one-tile-ahead; single barrier per tile.
// SMEM: Q @0 (8K), K0 @8192, K1 @16384, V0 @24576, V1 @32768 (8K each),
//       madd @40960 (512B).  Total 41,472 B -> 2 CTAs/SM, 4 warps/SMSP.
// ---------------------------------------------------------------------------
#define ATT_SMEM 41472

__global__ __launch_bounds__(256, 2)
void attn_tc(const unsigned int* __restrict__ mask, __half* __restrict__ out)
{
    extern __shared__ char smc[];
    const uint32_t sb  = smem_u32(smc);
    const uint32_t QB  = sb;
    const uint32_t KB0 = sb + 8192;
    const uint32_t VB0 = sb + 24576;
    float* maddf = (float*)(smc + 40960);

    const int t    = threadIdx.x;
    const int w    = t >> 5;
    const int lane = t & 31;
    const int g    = lane >> 2;
    const int t4   = lane & 3;
    const int i7   = lane & 7;
    const int tq   = lane >> 3;
    const int wq   = w & 3;        // q-group
    const int wk   = w >> 2;       // key half (0/1)
    const int q0   = blockIdx.x * 64;
    const int h    = blockIdx.y;
    const int b    = blockIdx.z;
    const int m0   = wq * 16;      // 16 query rows per q-group
    const int kn0  = wk * 32;      // 32 keys per key-half

    const float BSC = ALPHA * LOG2E / (float)S_LEN;

    // ldmatrix per-lane row bases (bytes; 128B rows)
    const uint32_t laneA  = (uint32_t)(m0 + ((tq & 1) << 3) + i7) * 128;   // Q rows
    const uint32_t laneBK = (uint32_t)(kn0 + ((tq & 2) << 2) + i7) * 128;  // K rows (this half)
    const uint32_t laneBV = (uint32_t)(((tq & 2) << 2) + i7) * 128;        // V^T rows (d)

    // prologue: Q + K(0) + V(0) (2 cp16 each per thread); madd[0]
#pragma unroll
    for (int i = 0; i < 2; i++) {
        int idx = i * 256 + t;
        int row = idx >> 3;
        int wd  = idx & 7;
        uint32_t so = (uint32_t)(row * 128 + ((wd ^ (row & 7)) << 4));
        cp16(QB + so,  &g_Q[((size_t)(b * S_LEN + q0 + row)) * E_DIM + h * D_HEAD + wd * 8]);
        cp16(KB0 + so, &g_K[((size_t)(b * S_LEN + row)) * E_DIM + h * D_HEAD + wd * 8]);
        cp16(VB0 + so, &g_V[((size_t)(b * 1024 + h * D_HEAD + row)) * S_LEN + wd * 8]);
    }
    cp_commit();
    if (t < 64)
        maddf[t] = (mask[b * S_LEN + t] != 0u) ? -1e30f : 0.0f;

    float o[8][4];
#pragma unroll
    for (int nf = 0; nf < 8; nf++)
#pragma unroll
        for (int r = 0; r < 4; r++) o[nf][r] = 0.0f;

    float lp0 = 0.0f, lp1 = 0.0f;
    const float tgtA = (float)(S_LEN - 1 - (q0 + m0 + g));
    const float tgtB = tgtA - 8.0f;

    for (int kt = 0; kt < 32; kt++) {
        const int k0g = kt * 64;
        const uint32_t KB  = KB0 + ((uint32_t)(kt & 1) << 13);
        const uint32_t VBc = VB0 + ((uint32_t)(kt & 1) << 13);

        // single sync point: K(kt), V(kt) complete + visible; alt buffers free
        cp_wait0();
        __syncthreads();

        // issue K(kt+1), V(kt+1), mask(kt+1)
        if (kt < 31) {
            const uint32_t KBn = KB0 + ((uint32_t)(~kt & 1) << 13);
            const uint32_t VBn = VB0 + ((uint32_t)(~kt & 1) << 13);
#pragma unroll
            for (int i = 0; i < 2; i++) {
                int idx = i * 256 + t;
                int row = idx >> 3;
                int wd  = idx & 7;
                uint32_t so = (uint32_t)(row * 128 + ((wd ^ (row & 7)) << 4));
                cp16(KBn + so,
                     &g_K[((size_t)(b * S_LEN + k0g + 64 + row)) * E_DIM + h * D_HEAD + wd * 8]);
                cp16(VBn + so,
                     &g_V[((size_t)(b * 1024 + h * D_HEAD + row)) * S_LEN + k0g + 64 + wd * 8]);
            }
            cp_commit();
            if (t < 64)
                maddf[(~kt & 1) * 64 + t] =
                    (mask[b * S_LEN + k0g + 64 + t] != 0u) ? -1e30f : 0.0f;
        }

        const float* md = maddf + (kt & 1) * 64;

        // ---- QK: 16 q-rows x 32 keys (this warp's half) ----
        float sc[4][4];
#pragma unroll
        for (int nf = 0; nf < 4; nf++)
#pragma unroll
            for (int r = 0; r < 4; r++) sc[nf][r] = 0.0f;

#pragma unroll
        for (int ks = 0; ks < 4; ks++) {
            const uint32_t cwA = (uint32_t)(((2 * ks + (tq >> 1)) ^ i7) << 4);
            const uint32_t cwB = (uint32_t)(((2 * ks + (tq & 1)) ^ i7) << 4);
            uint32_t av[4];
            LDSM4(av, QB + laneA + cwA);
            uint32_t bv[8];
#pragma unroll
            for (int np = 0; np < 2; np++)
                LDSM4(&bv[np * 4], KB + laneBK + np * 2048 + cwB);
#pragma unroll
            for (int nf = 0; nf < 4; nf++) {
                uint32_t b0 = bv[(nf >> 1) * 4 + (nf & 1) * 2];
                uint32_t b1 = bv[(nf >> 1) * 4 + (nf & 1) * 2 + 1];
                mma8(sc[nf], av, b0, b1);
            }
        }

        // ---- softmax (no max): p = ex2(s + bias + mask); register P ----
        uint32_t pa[8];
        float s0 = 0.0f, s1 = 0.0f;
#pragma unroll
        for (int nf = 0; nf < 4; nf++) {
            int jc = kn0 + nf * 8 + 2 * t4;
            float jk0 = (float)(k0g + jc);
            float2 ma = *(const float2*)&md[jc];
            float p0 = ex2(sc[nf][0] - BSC * fabsf(jk0 - tgtA) + ma.x);
            float p1 = ex2(sc[nf][1] - BSC * fabsf(jk0 + 1.0f - tgtA) + ma.y);
            float p2 = ex2(sc[nf][2] - BSC * fabsf(jk0 - tgtB) + ma.x);
            float p3 = ex2(sc[nf][3] - BSC * fabsf(jk0 + 1.0f - tgtB) + ma.y);
            s0 += p0 + p1;
            s1 += p2 + p3;
            pa[2 * nf]     = packh2(p0, p1);   // rows g
            pa[2 * nf + 1] = packh2(p2, p3);   // rows g+8
        }
        lp0 += s0;
        lp1 += s1;

        // ---- O += P @ V over this warp's 32 keys (2 k-steps of 16) ----
#pragma unroll
        for (int ks2 = 0; ks2 < 2; ks2++) {
            const uint32_t cwBV =
                (uint32_t)(((4 * wk + 2 * ks2 + (tq & 1)) ^ i7) << 4);
            uint32_t bvv[16];
#pragma unroll
            for (int np = 0; np < 4; np++)
                LDSM4(&bvv[np * 4], VBc + laneBV + np * 2048 + cwBV);
#pragma unroll
            for (int nf = 0; nf < 8; nf++) {
                uint32_t b0 = bvv[(nf >> 1) * 4 + (nf & 1) * 2];
                uint32_t b1 = bvv[(nf >> 1) * 4 + (nf & 1) * 2 + 1];
                mma8(o[nf], &pa[4 * ks2], b0, b1);
            }
        }
    }

    // ---- combine key halves: wk=1 stages partial O + lp; wk=0 adds ----
    __syncthreads();   // all tiles done; K/V smem reusable
    float* ostage = (float*)(smc + 8192);          // 4 warps x 4KB = 16KB
    float* lstage = (float*)(smc + 24576);         // 4 warps x 256B
    if (wk == 1) {
#pragma unroll
        for (int nf = 0; nf < 8; nf++)
#pragma unroll
            for (int r = 0; r < 4; r++)
                ostage[wq * 1024 + (nf * 4 + r) * 32 + lane] = o[nf][r];
        lstage[wq * 64 + lane] = lp0;
        lstage[wq * 64 + 32 + lane] = lp1;
    }
    __syncthreads();
    if (wk == 0) {
#pragma unroll
        for (int nf = 0; nf < 8; nf++)
#pragma unroll
            for (int r = 0; r < 4; r++)
                o[nf][r] += ostage[wq * 1024 + (nf * 4 + r) * 32 + lane];
        lp0 += lstage[wq * 64 + lane];
        lp1 += lstage[wq * 64 + 32 + lane];

        lp0 += __shfl_xor_sync(0xffffffffu, lp0, 1);
        lp0 += __shfl_xor_sync(0xffffffffu, lp0, 2);
        lp1 += __shfl_xor_sync(0xffffffffu, lp1, 1);
        lp1 += __shfl_xor_sync(0xffffffffu, lp1, 2);
        float inv0 = 1.0f / lp0;
        float inv1 = 1.0f / lp1;
        size_t r0 = ((size_t)(b * S_LEN + q0 + m0 + g)) * E_DIM + h * D_HEAD;
        size_t r1 = r0 + 8 * E_DIM;
#pragma unroll
        for (int nf = 0; nf < 8; nf++) {
            int col = nf * 8 + 2 * t4;
            *(__half2*)&out[r0 + col] =
                __floats2half2_rn(o[nf][0] * inv0, o[nf][1] * inv0);
            *(__half2*)&out[r1 + col] =
                __floats2half2_rn(o[nf][2] * inv1, o[nf][3] * inv1);
        }
    }
}

// ---------------------------------------------------------------------------
extern "C" void kernel_launch(void* const* d_in, const int* in_sizes, int n_in,
                              void* d_out, int out_size)
{
    const float* x    = (const float*)d_in[0];
    const float* Wq   = (const float*)d_in[1];
    const float* Wk   = (const float*)d_in[2];
    const float* Wv   = (const float*)d_in[3];
    const float* Wo   = (const float*)d_in[4];
    const unsigned int* mask = (const unsigned int*)d_in[5];
    float* out = (float*)d_out;

    __half *xp, *wqp, *wkp, *wvp, *wop, *qp, *kp, *vp, *ap;
    cudaGetSymbolAddress((void**)&xp,  g_X);
    cudaGetSymbolAddress((void**)&wqp, g_Wq);
    cudaGetSymbolAddress((void**)&wkp, g_Wk);
    cudaGetSymbolAddress((void**)&wvp, g_Wv);
    cudaGetSymbolAddress((void**)&wop, g_Wo);
    cudaGetSymbolAddress((void**)&qp,  g_Q);
    cudaGetSymbolAddress((void**)&kp,  g_K);
    cudaGetSymbolAddress((void**)&vp,  g_V);
    cudaGetSymbolAddress((void**)&ap,  g_A);

    cudaFuncSetAttribute(gemm_tc, cudaFuncAttributeMaxDynamicSharedMemorySize, GEMM_SMEM);
    cudaFuncSetAttribute(attn_tc, cudaFuncAttributeMaxDynamicSharedMemorySize, ATT_SMEM);

    // 1. pre-convert inputs to fp16 (Wq scaled by 0.125*log2e)
    cvt_kernel<<<dim3(512, 1, 5), 256>>>((const float4*)x, (const float4*)Wq,
                                         (const float4*)Wk, (const float4*)Wv,
                                         (const float4*)Wo);

    // 2. fused QKV projections (V written transposed)
    gemm_tc<<<dim3(GN / 128, GM / 128, 3), 128, GEMM_SMEM>>>(
        xp, wqp, wkp, wvp, qp, kp, vp, 1);

    // 3. attention (key-split warps: 4 q-groups x 2 key halves)
    attn_tc<<<dim3(S_LEN / 64, H_NUM, B_SZ), 256, ATT_SMEM>>>(mask, ap);

    // 4. output projection (fp32 out)
    gemm_tc<<<dim3(GN / 128, GM / 128, 1), 128, GEMM_SMEM>>>(
        ap, wop, wop, wop, out, out, out, 0);
}